// round 1
// baseline (speedup 1.0000x reference)
#include <cuda_runtime.h>
#include <cstdint>

#define SEQ   1000
#define IDIM  900
#define HDIM  4096
#define WOLD  (HDIM + IDIM + 1)   // 4997, W_out row stride
#define NBLK  148
#define TPB   1024
#define CACHE_ROWS 13
#define LOOP_SMEM ((CACHE_ROWS * HDIM + HDIM) * sizeof(float))   // 229376 B

// ---------------- scratch (static device globals; no allocation) ----------------
__device__ float g_U[SEQ * HDIM];   // W_ih @ inp[t]   (t-major)
__device__ float g_P[SEQ * IDIM];   // bias + input part of readout
__device__ int   g_flags[NBLK];

__device__ __forceinline__ int ld_acq(const int* p) {
    int v;
    asm volatile("ld.acquire.gpu.b32 %0, [%1];" : "=r"(v) : "l"(p) : "memory");
    return v;
}
__device__ __forceinline__ void st_rel(int* p, int v) {
    asm volatile("st.release.gpu.b32 [%0], %1;" :: "l"(p), "r"(v) : "memory");
}

__global__ void reset_kernel() {
    if (threadIdx.x < NBLK) g_flags[threadIdx.x] = 0;
}

// ---------------- persistent recurrence kernel ----------------
// s_{t} = tanh(U[t] + W_hh @ s_{t-1});  states[t] = s_t
// 148 blocks (1/SM), rows of W_hh partitioned across blocks; first CACHE_ROWS
// rows of each block's slice live in SMEM for the whole run.
__global__ __launch_bounds__(TPB, 1) void esn_loop_kernel(
    const float* __restrict__ W_hh,
    const float* __restrict__ s0,
    float* __restrict__ states)
{
    extern __shared__ float sh[];
    float* w_sh = sh;                      // CACHE_ROWS * HDIM
    float* s_sh = sh + CACHE_ROWS * HDIM;  // HDIM

    const int bid  = blockIdx.x;
    const int tid  = threadIdx.x;
    const int warp = tid >> 5;
    const int lane = tid & 31;

    // 4096 = 148*27 + 100 -> blocks 0..99 get 28 rows, 100..147 get 27
    const int base  = bid * 27 + (bid < 100 ? bid : 100);
    const int nrows = (bid < 100) ? 28 : 27;

    // prologue: cache first CACHE_ROWS rows of this block's slice in SMEM
    {
        const float4* wsrc = (const float4*)(W_hh + (size_t)base * HDIM);
        float4* wdst = (float4*)w_sh;
        for (int i = tid; i < CACHE_ROWS * (HDIM / 4); i += TPB) wdst[i] = wsrc[i];
    }

    const float* s_src = s0;

    for (int t = 0; t < SEQ; ++t) {
        __syncthreads();   // w_sh/s_sh consumers of previous step done
        // stage current state vector into SMEM (HDIM/4 == TPB exactly)
        ((float4*)s_sh)[tid] = ((const float4*)s_src)[tid];
        __syncthreads();

        // each warp computes 2 rows, sharing the s loads
        const int r0 = 2 * warp;
        if (r0 < nrows) {
            const int r1 = r0 + 1;
            const bool has1 = (r1 < nrows);
            const float4* w0 = (r0 < CACHE_ROWS)
                ? (const float4*)(w_sh + r0 * HDIM)
                : (const float4*)(W_hh + (size_t)(base + r0) * HDIM);
            const float4* w1 = !has1 ? w0 : ((r1 < CACHE_ROWS)
                ? (const float4*)(w_sh + r1 * HDIM)
                : (const float4*)(W_hh + (size_t)(base + r1) * HDIM));
            const float4* sv = (const float4*)s_sh;

            float acc0 = 0.f, acc1 = 0.f;
            #pragma unroll 4
            for (int kk = lane; kk < HDIM / 4; kk += 32) {
                float4 s = sv[kk];
                float4 a = w0[kk];
                float4 b = w1[kk];
                acc0 = fmaf(a.x, s.x, acc0); acc0 = fmaf(a.y, s.y, acc0);
                acc0 = fmaf(a.z, s.z, acc0); acc0 = fmaf(a.w, s.w, acc0);
                acc1 = fmaf(b.x, s.x, acc1); acc1 = fmaf(b.y, s.y, acc1);
                acc1 = fmaf(b.z, s.z, acc1); acc1 = fmaf(b.w, s.w, acc1);
            }
            #pragma unroll
            for (int off = 16; off; off >>= 1) {
                acc0 += __shfl_xor_sync(0xffffffffu, acc0, off);
                acc1 += __shfl_xor_sync(0xffffffffu, acc1, off);
            }
            if (lane == 0) {
                const size_t o = (size_t)t * HDIM + base;
                states[o + r0] = tanhf(acc0 + g_U[o + r0]);
                if (has1) states[o + r1] = tanhf(acc1 + g_U[o + r1]);
            }
        }

        // grid barrier: release flag, acquire-poll all flags
        __syncthreads();
        if (tid == 0) { __threadfence(); st_rel(&g_flags[bid], t + 1); }
        if (tid < NBLK) {
            while (ld_acq(&g_flags[tid]) <= t) { __nanosleep(32); }
        }
        __syncthreads();

        s_src = states + (size_t)t * HDIM;
    }
}

// ---------------- generic fp32 GEMM: C[n][m] = (bias[m]) + (Cadd[n][m]) + sum_k A[m][k]*B[n][k]
// A: M x K (row stride lda, possibly unaligned base -> scalar loads)
// B: N x K (row stride ldb, 16B-aligned rows)
__global__ void gemm_nt_kernel(
    const float* __restrict__ A, int lda,
    const float* __restrict__ B, int ldb,
    float* __restrict__ C, int ldc,
    const float* __restrict__ Cadd,
    const float* __restrict__ bias, int bias_stride,
    int M, int N, int K)
{
    const int BM = 128, BN = 64, BK = 16;
    __shared__ float As[128][BK + 1];
    __shared__ float Bs[64][BK + 1];

    const int tid = threadIdx.x;          // 256 threads
    const int tx = tid & 15;              // n direction
    const int ty = tid >> 4;              // m direction
    const int m0 = blockIdx.x * BM;
    const int n0 = blockIdx.y * BN;

    float acc[8][4];
    #pragma unroll
    for (int j = 0; j < 8; ++j)
        #pragma unroll
        for (int i = 0; i < 4; ++i) acc[j][i] = 0.f;

    for (int kt = 0; kt < K; kt += BK) {
        // --- load A tile (scalar loads: A base may be 4B-aligned only) ---
        #pragma unroll
        for (int it = 0; it < 2; ++it) {
            int idx = it * 256 + tid;       // 0..511
            int m = idx >> 2;               // 0..127
            int kq = (idx & 3) * 4;         // 0,4,8,12
            int gm = m0 + m;
            int gk = kt + kq;
            float v0 = 0.f, v1 = 0.f, v2 = 0.f, v3 = 0.f;
            if (gm < M) {
                const float* p = A + (size_t)gm * lda + gk;
                int rem = K - gk;
                if (rem >= 4)      { v0 = p[0]; v1 = p[1]; v2 = p[2]; v3 = p[3]; }
                else if (rem > 0)  { v0 = p[0];
                                     if (rem > 1) v1 = p[1];
                                     if (rem > 2) v2 = p[2]; }
            }
            As[m][kq] = v0; As[m][kq + 1] = v1; As[m][kq + 2] = v2; As[m][kq + 3] = v3;
        }
        // --- load B tile (rows 16B-aligned: float4 on full quads) ---
        {
            int n = tid >> 2;               // 0..63
            int kq = (tid & 3) * 4;
            int gn = n0 + n;
            int gk = kt + kq;
            float v0 = 0.f, v1 = 0.f, v2 = 0.f, v3 = 0.f;
            if (gn < N) {
                const float* p = B + (size_t)gn * ldb + gk;
                int rem = K - gk;
                if (rem >= 4) {
                    float4 v = *(const float4*)p;
                    v0 = v.x; v1 = v.y; v2 = v.z; v3 = v.w;
                } else if (rem > 0) {
                    v0 = p[0];
                    if (rem > 1) v1 = p[1];
                    if (rem > 2) v2 = p[2];
                }
            }
            Bs[n][kq] = v0; Bs[n][kq + 1] = v1; Bs[n][kq + 2] = v2; Bs[n][kq + 3] = v3;
        }
        __syncthreads();

        #pragma unroll
        for (int kk = 0; kk < BK; ++kk) {
            float a[8], b[4];
            #pragma unroll
            for (int j = 0; j < 8; ++j) a[j] = As[ty * 8 + j][kk];
            #pragma unroll
            for (int i = 0; i < 4; ++i) b[i] = Bs[tx * 4 + i][kk];
            #pragma unroll
            for (int j = 0; j < 8; ++j)
                #pragma unroll
                for (int i = 0; i < 4; ++i)
                    acc[j][i] = fmaf(a[j], b[i], acc[j][i]);
        }
        __syncthreads();
    }

    // epilogue
    #pragma unroll
    for (int j = 0; j < 8; ++j) {
        int gm = m0 + ty * 8 + j;
        if (gm >= M) continue;
        float bv = bias ? bias[(size_t)gm * bias_stride] : 0.f;
        #pragma unroll
        for (int i = 0; i < 4; ++i) {
            int gn = n0 + tx * 4 + i;
            if (gn >= N) continue;
            float v = acc[j][i] + bv;
            if (Cadd) v += Cadd[(size_t)gn * ldc + gm];
            C[(size_t)gn * ldc + gm] = v;
        }
    }
}

// ---------------- launch ----------------
extern "C" void kernel_launch(void* const* d_in, const int* in_sizes, int n_in,
                              void* d_out, int out_size)
{
    const float* inputs = (const float*)d_in[0];  // (1000,1,900)
    const float* state0 = (const float*)d_in[1];  // (1,4096)
    const float* W_ih   = (const float*)d_in[2];  // (4096,900)
    const float* W_hh   = (const float*)d_in[3];  // (4096,4096)
    const float* W_out  = (const float*)d_in[4];  // (900,4997)

    float* out    = (float*)d_out;                // outputs: SEQ*IDIM
    float* states = out + (size_t)SEQ * IDIM;     // states : SEQ*HDIM

    float *U = nullptr, *P = nullptr;
    cudaGetSymbolAddress((void**)&U, g_U);
    cudaGetSymbolAddress((void**)&P, g_P);

    cudaFuncSetAttribute(esn_loop_kernel,
                         cudaFuncAttributeMaxDynamicSharedMemorySize, (int)LOOP_SMEM);

    reset_kernel<<<1, 256>>>();

    dim3 blk(256);
    // U[t][h] = W_ih[h,:] . inp[t,:]
    gemm_nt_kernel<<<dim3((HDIM + 127) / 128, (SEQ + 63) / 64), blk>>>(
        W_ih, IDIM, inputs, IDIM, U, HDIM,
        nullptr, nullptr, 0, HDIM, SEQ, IDIM);

    // P[t][i] = W_out[i][0] + W_out[i,1:901] . inp[t,:]
    gemm_nt_kernel<<<dim3((IDIM + 127) / 128, (SEQ + 63) / 64), blk>>>(
        W_out + 1, WOLD, inputs, IDIM, P, IDIM,
        nullptr, W_out, WOLD, IDIM, SEQ, IDIM);

    // sequential recurrence: states[t] = tanh(U[t] + W_hh @ states[t-1])
    esn_loop_kernel<<<NBLK, TPB, LOOP_SMEM>>>(W_hh, state0, states);

    // out[t][i] = P[t][i] + W_out[i,901:] . states[t,:]
    gemm_nt_kernel<<<dim3((IDIM + 127) / 128, (SEQ + 63) / 64), blk>>>(
        W_out + 1 + IDIM, WOLD, states, HDIM, out, IDIM,
        P, nullptr, 0, IDIM, SEQ, HDIM);
}